// round 3
// baseline (speedup 1.0000x reference)
#include <cuda_runtime.h>
#include <math.h>

#define C_DIM 1280
#define B_DIM 2
#define S_DIM 2048
#define H_DIM 20
#define D_DIM 64
#define R_DIM 16
#define M_DIM (B_DIM * S_DIM)       /* 4096 */
#define SCALE_F 0.125f              /* 1/sqrt(64) */

// ------------------------- scratch (__device__ globals; no allocs) ----------
__device__ float g_weff[4 * C_DIM * C_DIM];      // effective weights, [n][k] layout
__device__ float g_qkv[3 * M_DIM * C_DIM];       // Q, K, V in [B,S,C] layout
__device__ float g_attno[M_DIM * C_DIM];         // attention output [B,S,C]

// ------------------------- Weff = W + B@A ----------------------------------
__global__ void build_weff_kernel(
    const float* __restrict__ Wq, const float* __restrict__ Wk,
    const float* __restrict__ Wv, const float* __restrict__ Wo,
    const float* __restrict__ Aq, const float* __restrict__ Bq,
    const float* __restrict__ Ak, const float* __restrict__ Bk,
    const float* __restrict__ Av, const float* __restrict__ Bv,
    const float* __restrict__ Ao, const float* __restrict__ Bo)
{
    int mat = blockIdx.y;
    int rem = blockIdx.x * blockDim.x + threadIdx.x;
    if (rem >= C_DIM * C_DIM) return;
    const float *W, *A, *Bu;
    if (mat == 0)      { W = Wq; A = Aq; Bu = Bq; }
    else if (mat == 1) { W = Wk; A = Ak; Bu = Bk; }
    else if (mat == 2) { W = Wv; A = Av; Bu = Bv; }
    else               { W = Wo; A = Ao; Bu = Bo; }
    int n = rem / C_DIM;
    int k = rem - n * C_DIM;
    float acc = W[rem];
#pragma unroll
    for (int r = 0; r < R_DIM; r++)
        acc += A[r * C_DIM + k] * Bu[n * R_DIM + r];
    g_weff[(size_t)mat * C_DIM * C_DIM + rem] = acc;
}

// ------------------------- C = A @ Bt^T (+bias) -----------------------------
// A: [M,K] row-major.  Bt: [N,K] row-major (i.e. B transposed already).
// 128x128 tile, BK=8, 256 threads, 8x8 micro-tile with 4+4 split columns.
#define BM 128
#define BN 128
#define BKT 8
__global__ __launch_bounds__(256) void sgemm_bt_kernel(
    const float* __restrict__ A, const float* __restrict__ Bt,
    const float* __restrict__ bias, float* __restrict__ Cout,
    int M, int N, int Kd, long bStride, long cStride)
{
    __shared__ float As[BKT][BM];
    __shared__ float Bs[BKT][BN];

    const float* Bz = Bt + (long)blockIdx.z * bStride;
    float* Cz = Cout + (long)blockIdx.z * cStride;

    int tid = threadIdx.x;
    int tx = tid & 15, ty = tid >> 4;
    int m0 = blockIdx.y * BM, n0 = blockIdx.x * BN;

    int lrow = tid >> 1;               // 0..127
    int lk4 = (tid & 1) * 4;           // 0 or 4
    const float* Ap = A  + (long)(m0 + lrow) * Kd + lk4;
    const float* Bp = Bz + (long)(n0 + lrow) * Kd + lk4;

    float acc[8][8];
#pragma unroll
    for (int i = 0; i < 8; i++)
#pragma unroll
        for (int j = 0; j < 8; j++) acc[i][j] = 0.f;

    for (int k0 = 0; k0 < Kd; k0 += BKT) {
        float4 av = *(const float4*)(Ap + k0);
        float4 bv = *(const float4*)(Bp + k0);
        As[lk4 + 0][lrow] = av.x; As[lk4 + 1][lrow] = av.y;
        As[lk4 + 2][lrow] = av.z; As[lk4 + 3][lrow] = av.w;
        Bs[lk4 + 0][lrow] = bv.x; Bs[lk4 + 1][lrow] = bv.y;
        Bs[lk4 + 2][lrow] = bv.z; Bs[lk4 + 3][lrow] = bv.w;
        __syncthreads();
#pragma unroll
        for (int kk = 0; kk < BKT; kk++) {
            float a[8], b[8];
            *(float4*)&a[0] = *(const float4*)&As[kk][ty * 4];
            *(float4*)&a[4] = *(const float4*)&As[kk][64 + ty * 4];
            *(float4*)&b[0] = *(const float4*)&Bs[kk][tx * 4];
            *(float4*)&b[4] = *(const float4*)&Bs[kk][64 + tx * 4];
#pragma unroll
            for (int i = 0; i < 8; i++)
#pragma unroll
                for (int j = 0; j < 8; j++)
                    acc[i][j] += a[i] * b[j];
        }
        __syncthreads();
    }

#pragma unroll
    for (int ih = 0; ih < 2; ih++)
#pragma unroll
        for (int i = 0; i < 4; i++) {
            int m = m0 + ih * 64 + ty * 4 + i;
#pragma unroll
            for (int jh = 0; jh < 2; jh++) {
                int n = n0 + jh * 64 + tx * 4;
                float4 v;
                v.x = acc[ih * 4 + i][jh * 4 + 0];
                v.y = acc[ih * 4 + i][jh * 4 + 1];
                v.z = acc[ih * 4 + i][jh * 4 + 2];
                v.w = acc[ih * 4 + i][jh * 4 + 3];
                if (bias) {
                    v.x += bias[n + 0]; v.y += bias[n + 1];
                    v.z += bias[n + 2]; v.w += bias[n + 3];
                }
                *(float4*)&Cz[(long)m * N + n] = v;
            }
        }
}

// ------------------------- flash attention ---------------------------------
// grid (S/64, H, B), 256 threads. BQ=BKV=64, D=64. Online softmax.
#define LDP 65
__global__ __launch_bounds__(256) void flash_kernel(
    const float* __restrict__ Qb, const float* __restrict__ Kb,
    const float* __restrict__ Vb, float* __restrict__ Ob)
{
    extern __shared__ float sm[];
    float* Qs    = sm;                       // 64*65
    float* Ks    = sm + 64 * LDP;            // 64*65
    float* Vs    = sm + 2 * 64 * LDP;        // 64*65
    float* Ps    = sm + 3 * 64 * LDP;        // 64*65
    float* red   = sm + 4 * 64 * LDP;        // 64*16
    float* mprev = red + 64 * 16;            // 64
    float* lrow  = mprev + 64;               // 64
    float* fct   = lrow + 64;                // 64
    float* mnew  = fct + 64;                 // 64

    int tid = threadIdx.x;
    int tx = tid & 15, ty = tid >> 4;
    int q0 = blockIdx.x * 64;
    int h  = blockIdx.y;
    int b  = blockIdx.z;
    long baseoff = ((long)b * S_DIM) * C_DIM + (long)h * D_DIM;

    // load Q tile (scaled)
    const float* Qg = Qb + baseoff + (long)q0 * C_DIM;
    for (int t = tid; t < 64 * 16; t += 256) {
        int row = t >> 4;
        int c4 = (t & 15) << 2;
        float4 v = *(const float4*)(Qg + (long)row * C_DIM + c4);
        float* d = &Qs[row * LDP + c4];
        d[0] = v.x * SCALE_F; d[1] = v.y * SCALE_F;
        d[2] = v.z * SCALE_F; d[3] = v.w * SCALE_F;
    }
    if (tid < 64) { mprev[tid] = -1e30f; lrow[tid] = 0.f; }

    float o[4][4];
#pragma unroll
    for (int i = 0; i < 4; i++)
#pragma unroll
        for (int j = 0; j < 4; j++) o[i][j] = 0.f;

    __syncthreads();

    for (int kt = 0; kt < S_DIM / 64; kt++) {
        const float* Kg = Kb + baseoff + (long)(kt * 64) * C_DIM;
        const float* Vg = Vb + baseoff + (long)(kt * 64) * C_DIM;
        for (int t = tid; t < 64 * 16; t += 256) {
            int row = t >> 4;
            int c4 = (t & 15) << 2;
            float4 kv = *(const float4*)(Kg + (long)row * C_DIM + c4);
            float4 vv = *(const float4*)(Vg + (long)row * C_DIM + c4);
            float* dk = &Ks[row * LDP + c4];
            dk[0] = kv.x; dk[1] = kv.y; dk[2] = kv.z; dk[3] = kv.w;
            float* dv = &Vs[row * LDP + c4];
            dv[0] = vv.x; dv[1] = vv.y; dv[2] = vv.z; dv[3] = vv.w;
        }
        __syncthreads();

        // scores S = Qs @ Ks^T   (already scaled)
        float s[4][4];
#pragma unroll
        for (int i = 0; i < 4; i++)
#pragma unroll
            for (int j = 0; j < 4; j++) s[i][j] = 0.f;
#pragma unroll 8
        for (int kk = 0; kk < 64; kk++) {
            float a0 = Qs[(ty * 4 + 0) * LDP + kk];
            float a1 = Qs[(ty * 4 + 1) * LDP + kk];
            float a2 = Qs[(ty * 4 + 2) * LDP + kk];
            float a3 = Qs[(ty * 4 + 3) * LDP + kk];
            float b0 = Ks[(tx * 4 + 0) * LDP + kk];
            float b1 = Ks[(tx * 4 + 1) * LDP + kk];
            float b2 = Ks[(tx * 4 + 2) * LDP + kk];
            float b3 = Ks[(tx * 4 + 3) * LDP + kk];
            s[0][0] += a0 * b0; s[0][1] += a0 * b1; s[0][2] += a0 * b2; s[0][3] += a0 * b3;
            s[1][0] += a1 * b0; s[1][1] += a1 * b1; s[1][2] += a1 * b2; s[1][3] += a1 * b3;
            s[2][0] += a2 * b0; s[2][1] += a2 * b1; s[2][2] += a2 * b2; s[2][3] += a2 * b3;
            s[3][0] += a3 * b0; s[3][1] += a3 * b1; s[3][2] += a3 * b2; s[3][3] += a3 * b3;
        }

        // local row max -> red
#pragma unroll
        for (int i = 0; i < 4; i++) {
            float lm = fmaxf(fmaxf(s[i][0], s[i][1]), fmaxf(s[i][2], s[i][3]));
            red[(ty * 4 + i) * 16 + tx] = lm;
        }
        __syncthreads();

        if (tid < 64) {
            float tm = red[tid * 16];
#pragma unroll
            for (int t = 1; t < 16; t++) tm = fmaxf(tm, red[tid * 16 + t]);
            float mo = mprev[tid];
            float mn = fmaxf(mo, tm);
            mnew[tid] = mn;
            fct[tid] = __expf(mo - mn);
            mprev[tid] = mn;
        }
        __syncthreads();

        // exponentiate + store P + local row sums
#pragma unroll
        for (int i = 0; i < 4; i++) {
            float mn = mnew[ty * 4 + i];
            float ls = 0.f;
#pragma unroll
            for (int j = 0; j < 4; j++) {
                float p = __expf(s[i][j] - mn);
                Ps[(ty * 4 + i) * LDP + tx * 4 + j] = p;
                ls += p;
            }
            red[(ty * 4 + i) * 16 + tx] = ls;
        }
        __syncthreads();

        if (tid < 64) {
            float ssum = 0.f;
#pragma unroll
            for (int t = 0; t < 16; t++) ssum += red[tid * 16 + t];
            lrow[tid] = lrow[tid] * fct[tid] + ssum;
        }

        // rescale O and accumulate O += P @ V
#pragma unroll
        for (int i = 0; i < 4; i++) {
            float f = fct[ty * 4 + i];
#pragma unroll
            for (int j = 0; j < 4; j++) o[i][j] *= f;
        }
#pragma unroll 8
        for (int key = 0; key < 64; key++) {
            float a0 = Ps[(ty * 4 + 0) * LDP + key];
            float a1 = Ps[(ty * 4 + 1) * LDP + key];
            float a2 = Ps[(ty * 4 + 2) * LDP + key];
            float a3 = Ps[(ty * 4 + 3) * LDP + key];
            float b0 = Vs[key * LDP + tx * 4 + 0];
            float b1 = Vs[key * LDP + tx * 4 + 1];
            float b2 = Vs[key * LDP + tx * 4 + 2];
            float b3 = Vs[key * LDP + tx * 4 + 3];
            o[0][0] += a0 * b0; o[0][1] += a0 * b1; o[0][2] += a0 * b2; o[0][3] += a0 * b3;
            o[1][0] += a1 * b0; o[1][1] += a1 * b1; o[1][2] += a1 * b2; o[1][3] += a1 * b3;
            o[2][0] += a2 * b0; o[2][1] += a2 * b1; o[2][2] += a2 * b2; o[2][3] += a2 * b3;
            o[3][0] += a3 * b0; o[3][1] += a3 * b1; o[3][2] += a3 * b2; o[3][3] += a3 * b3;
        }
        __syncthreads();
    }

    // finalize: divide by l, write to [B,S,C]
#pragma unroll
    for (int i = 0; i < 4; i++) {
        float inv = 1.0f / lrow[ty * 4 + i];
        long off = baseoff + (long)(q0 + ty * 4 + i) * C_DIM + tx * 4;
        float4 v;
        v.x = o[i][0] * inv; v.y = o[i][1] * inv;
        v.z = o[i][2] * inv; v.w = o[i][3] * inv;
        *(float4*)(Ob + off) = v;
    }
}

// ------------------------- launch ------------------------------------------
extern "C" void kernel_launch(void* const* d_in, const int* in_sizes, int n_in,
                              void* d_out, int out_size)
{
    const float* x  = (const float*)d_in[0];
    const float* Wq = (const float*)d_in[1];
    const float* Wk = (const float*)d_in[2];
    const float* Wv = (const float*)d_in[3];
    const float* Wo = (const float*)d_in[4];
    const float* bo = (const float*)d_in[5];
    const float* Aq = (const float*)d_in[6];
    const float* Bq = (const float*)d_in[7];
    const float* Ak = (const float*)d_in[8];
    const float* Bk = (const float*)d_in[9];
    const float* Av = (const float*)d_in[10];
    const float* Bv = (const float*)d_in[11];
    const float* Ao = (const float*)d_in[12];
    const float* Bo = (const float*)d_in[13];

    float *weff, *qkv, *attno;
    cudaGetSymbolAddress((void**)&weff, g_weff);
    cudaGetSymbolAddress((void**)&qkv, g_qkv);
    cudaGetSymbolAddress((void**)&attno, g_attno);

    // 1) effective weights
    build_weff_kernel<<<dim3((C_DIM * C_DIM) / 256, 4), 256>>>(
        Wq, Wk, Wv, Wo, Aq, Bq, Ak, Bk, Av, Bv, Ao, Bo);

    // 2) fused Q/K/V projections: [4096,1280] = x @ weff[z]^T
    const long wStride = (long)C_DIM * C_DIM;
    const long oStride = (long)M_DIM * C_DIM;
    sgemm_bt_kernel<<<dim3(C_DIM / BN, M_DIM / BM, 3), 256>>>(
        x, weff, nullptr, qkv, M_DIM, C_DIM, C_DIM, wStride, oStride);

    // 3) attention
    size_t smem = (size_t)(4 * 64 * LDP + 64 * 16 + 4 * 64) * sizeof(float);
    cudaFuncSetAttribute(flash_kernel,
                         cudaFuncAttributeMaxDynamicSharedMemorySize, (int)smem);
    flash_kernel<<<dim3(S_DIM / 64, H_DIM, B_DIM), 256, smem>>>(
        qkv, qkv + oStride, qkv + 2 * oStride, attno);

    // 4) output projection (+bias) straight into d_out
    sgemm_bt_kernel<<<dim3(C_DIM / BN, M_DIM / BM, 1), 256>>>(
        attno, weff + 3 * wStride, bo, (float*)d_out,
        M_DIM, C_DIM, C_DIM, 0, 0);
}

// round 5
// speedup vs baseline: 1.1315x; 1.1315x over previous
#include <cuda_runtime.h>
#include <math.h>

#define C_DIM 1280
#define B_DIM 2
#define S_DIM 2048
#define H_DIM 20
#define D_DIM 64
#define R_DIM 16
#define M_DIM (B_DIM * S_DIM)       /* 4096 */
#define SCALE_F 0.125f              /* 1/sqrt(64) */

// ------------------------- scratch (__device__ globals; no allocs) ----------
__device__ float g_weff[4 * C_DIM * C_DIM];      // effective weights, [n][k] layout
__device__ float g_qkv[3 * M_DIM * C_DIM];       // Q, K, V in [B,S,C] layout
__device__ float g_attno[M_DIM * C_DIM];         // attention output [B,S,C]

// ------------------------- Weff = W + B@A ----------------------------------
__global__ void build_weff_kernel(
    const float* __restrict__ Wq, const float* __restrict__ Wk,
    const float* __restrict__ Wv, const float* __restrict__ Wo,
    const float* __restrict__ Aq, const float* __restrict__ Bq,
    const float* __restrict__ Ak, const float* __restrict__ Bk,
    const float* __restrict__ Av, const float* __restrict__ Bv,
    const float* __restrict__ Ao, const float* __restrict__ Bo)
{
    int mat = blockIdx.y;
    int rem = blockIdx.x * blockDim.x + threadIdx.x;
    if (rem >= C_DIM * C_DIM) return;
    const float *W, *A, *Bu;
    if (mat == 0)      { W = Wq; A = Aq; Bu = Bq; }
    else if (mat == 1) { W = Wk; A = Ak; Bu = Bk; }
    else if (mat == 2) { W = Wv; A = Av; Bu = Bv; }
    else               { W = Wo; A = Ao; Bu = Bo; }
    int n = rem / C_DIM;
    int k = rem - n * C_DIM;
    float acc = W[rem];
#pragma unroll
    for (int r = 0; r < R_DIM; r++)
        acc += A[r * C_DIM + k] * Bu[n * R_DIM + r];
    g_weff[(size_t)mat * C_DIM * C_DIM + rem] = acc;
}

// ------------------------- C = A @ Bt^T (+bias) -----------------------------
// A: [M,K] row-major.  Bt: [N,K] row-major.
// 128x128 tile, BK=16, 256 threads, 8x8 micro, DOUBLE-BUFFERED smem +
// register prefetch of the next k-tile. One __syncthreads per 16-k.
#define BM 128
#define BN 128
#define BKT 16
#define LDA 132
__global__ __launch_bounds__(256, 2) void sgemm_bt_kernel(
    const float* __restrict__ A, const float* __restrict__ Bt,
    const float* __restrict__ bias, float* __restrict__ Cout,
    int M, int N, int Kd, long bStride, long cStride)
{
    __shared__ float As[2][BKT][LDA];
    __shared__ float Bs[2][BKT][LDA];

    const float* Bz = Bt + (long)blockIdx.z * bStride;
    float* Cz = Cout + (long)blockIdx.z * cStride;

    int tid = threadIdx.x;
    int tx = tid & 15, ty = tid >> 4;
    int m0 = blockIdx.y * BM, n0 = blockIdx.x * BN;

    int lrow = tid >> 1;               // 0..127
    int lk8 = (tid & 1) * 8;           // 0 or 8
    const float* Ap = A  + (long)(m0 + lrow) * Kd + lk8;
    const float* Bp = Bz + (long)(n0 + lrow) * Kd + lk8;

    // preload k-tile 0 into buffer 0
    float4 ra0 = *(const float4*)(Ap);
    float4 ra1 = *(const float4*)(Ap + 4);
    float4 rb0 = *(const float4*)(Bp);
    float4 rb1 = *(const float4*)(Bp + 4);
    As[0][lk8 + 0][lrow] = ra0.x; As[0][lk8 + 1][lrow] = ra0.y;
    As[0][lk8 + 2][lrow] = ra0.z; As[0][lk8 + 3][lrow] = ra0.w;
    As[0][lk8 + 4][lrow] = ra1.x; As[0][lk8 + 5][lrow] = ra1.y;
    As[0][lk8 + 6][lrow] = ra1.z; As[0][lk8 + 7][lrow] = ra1.w;
    Bs[0][lk8 + 0][lrow] = rb0.x; Bs[0][lk8 + 1][lrow] = rb0.y;
    Bs[0][lk8 + 2][lrow] = rb0.z; Bs[0][lk8 + 3][lrow] = rb0.w;
    Bs[0][lk8 + 4][lrow] = rb1.x; Bs[0][lk8 + 5][lrow] = rb1.y;
    Bs[0][lk8 + 6][lrow] = rb1.z; Bs[0][lk8 + 7][lrow] = rb1.w;
    __syncthreads();

    float acc[8][8];
#pragma unroll
    for (int i = 0; i < 8; i++)
#pragma unroll
        for (int j = 0; j < 8; j++) acc[i][j] = 0.f;

    int buf = 0;
    for (int k0 = BKT; k0 <= Kd; k0 += BKT) {
        bool more = (k0 < Kd);
        if (more) {                           // prefetch next tile (overlaps FMAs)
            ra0 = *(const float4*)(Ap + k0);
            ra1 = *(const float4*)(Ap + k0 + 4);
            rb0 = *(const float4*)(Bp + k0);
            rb1 = *(const float4*)(Bp + k0 + 4);
        }
#pragma unroll
        for (int kk = 0; kk < BKT; kk++) {
            float a[8], b[8];
            *(float4*)&a[0] = *(const float4*)&As[buf][kk][ty * 4];
            *(float4*)&a[4] = *(const float4*)&As[buf][kk][64 + ty * 4];
            *(float4*)&b[0] = *(const float4*)&Bs[buf][kk][tx * 4];
            *(float4*)&b[4] = *(const float4*)&Bs[buf][kk][64 + tx * 4];
#pragma unroll
            for (int i = 0; i < 8; i++)
#pragma unroll
                for (int j = 0; j < 8; j++)
                    acc[i][j] += a[i] * b[j];
        }
        if (more) {
            int nb = buf ^ 1;
            As[nb][lk8 + 0][lrow] = ra0.x; As[nb][lk8 + 1][lrow] = ra0.y;
            As[nb][lk8 + 2][lrow] = ra0.z; As[nb][lk8 + 3][lrow] = ra0.w;
            As[nb][lk8 + 4][lrow] = ra1.x; As[nb][lk8 + 5][lrow] = ra1.y;
            As[nb][lk8 + 6][lrow] = ra1.z; As[nb][lk8 + 7][lrow] = ra1.w;
            Bs[nb][lk8 + 0][lrow] = rb0.x; Bs[nb][lk8 + 1][lrow] = rb0.y;
            Bs[nb][lk8 + 2][lrow] = rb0.z; Bs[nb][lk8 + 3][lrow] = rb0.w;
            Bs[nb][lk8 + 4][lrow] = rb1.x; Bs[nb][lk8 + 5][lrow] = rb1.y;
            Bs[nb][lk8 + 6][lrow] = rb1.z; Bs[nb][lk8 + 7][lrow] = rb1.w;
            __syncthreads();
            buf = nb;
        }
    }

#pragma unroll
    for (int ih = 0; ih < 2; ih++)
#pragma unroll
        for (int i = 0; i < 4; i++) {
            int m = m0 + ih * 64 + ty * 4 + i;
#pragma unroll
            for (int jh = 0; jh < 2; jh++) {
                int n = n0 + jh * 64 + tx * 4;
                float4 v;
                v.x = acc[ih * 4 + i][jh * 4 + 0];
                v.y = acc[ih * 4 + i][jh * 4 + 1];
                v.z = acc[ih * 4 + i][jh * 4 + 2];
                v.w = acc[ih * 4 + i][jh * 4 + 3];
                if (bias) {
                    v.x += bias[n + 0]; v.y += bias[n + 1];
                    v.z += bias[n + 2]; v.w += bias[n + 3];
                }
                *(float4*)&Cz[(long)m * N + n] = v;
            }
        }
}

// ------------------------- flash attention ---------------------------------
// grid (S/64, H, B), 256 threads. BQ=BKV=64, D=64. Online softmax.
// float4 shared loads in both matmul phases; register prefetch of next K/V.
// QK phase score columns for thread (tx,ty): {tx, 16+tx, 32+tx, 48+tx}
// (lane-consecutive K rows -> near-conflict-free float4 LDS).
// PV phase output columns: tx*4..tx*4+3 (vectorized V rows). P bridges the
// two mappings through shared memory.
#define LDP 68
__global__ __launch_bounds__(256, 2) void flash_kernel(
    const float* __restrict__ Qb, const float* __restrict__ Kb,
    const float* __restrict__ Vb, float* __restrict__ Ob)
{
    extern __shared__ float sm[];
    float* Qs    = sm;                       // 64*68
    float* Ks    = sm + 64 * LDP;            // 64*68
    float* Vs    = sm + 2 * 64 * LDP;        // 64*68
    float* Ps    = sm + 3 * 64 * LDP;        // 64*68
    float* red   = sm + 4 * 64 * LDP;        // 64*16
    float* mprev = red + 64 * 16;            // 64
    float* lsum  = mprev + 64;               // 64
    float* fct   = lsum + 64;                // 64
    float* mnew  = fct + 64;                 // 64

    int tid = threadIdx.x;
    int tx = tid & 15, ty = tid >> 4;
    int q0 = blockIdx.x * 64;
    int h  = blockIdx.y;
    int b  = blockIdx.z;
    long baseoff = ((long)b * S_DIM) * C_DIM + (long)h * D_DIM;

    const float* Qg = Qb + baseoff + (long)q0 * C_DIM;
    const float* Kg = Kb + baseoff;
    const float* Vg = Vb + baseoff;

    // load Q tile (scaled) + prefetch K/V tile 0 into regs
    float4 kreg[4], vreg[4];
#pragma unroll
    for (int p = 0; p < 4; p++) {
        int idx = tid + p * 256;
        int row = idx >> 4;
        int c4 = (idx & 15) << 2;
        kreg[p] = *(const float4*)(Kg + (long)row * C_DIM + c4);
        vreg[p] = *(const float4*)(Vg + (long)row * C_DIM + c4);
        float4 v = *(const float4*)(Qg + (long)row * C_DIM + c4);
        float* d = &Qs[row * LDP + c4];
        d[0] = v.x * SCALE_F; d[1] = v.y * SCALE_F;
        d[2] = v.z * SCALE_F; d[3] = v.w * SCALE_F;
    }
    if (tid < 64) { mprev[tid] = -1e30f; lsum[tid] = 0.f; }
    __syncthreads();           // Q stored; also orders init
#pragma unroll
    for (int p = 0; p < 4; p++) {
        int idx = tid + p * 256;
        int row = idx >> 4;
        int c4 = (idx & 15) << 2;
        *(float4*)&Ks[row * LDP + c4] = kreg[p];
        *(float4*)&Vs[row * LDP + c4] = vreg[p];
    }
    __syncthreads();

    float o[4][4];
#pragma unroll
    for (int i = 0; i < 4; i++)
#pragma unroll
        for (int j = 0; j < 4; j++) o[i][j] = 0.f;

    for (int kt = 0; kt < S_DIM / 64; kt++) {
        bool more = (kt < S_DIM / 64 - 1);
        if (more) {            // prefetch next K/V tile into regs (overlaps compute)
            const float* Kn = Kg + (long)((kt + 1) * 64) * C_DIM;
            const float* Vn = Vg + (long)((kt + 1) * 64) * C_DIM;
#pragma unroll
            for (int p = 0; p < 4; p++) {
                int idx = tid + p * 256;
                int row = idx >> 4;
                int c4 = (idx & 15) << 2;
                kreg[p] = *(const float4*)(Kn + (long)row * C_DIM + c4);
                vreg[p] = *(const float4*)(Vn + (long)row * C_DIM + c4);
            }
        }

        // scores S = Qs @ Ks^T (already scaled). cols j*16+tx
        float s[4][4];
#pragma unroll
        for (int i = 0; i < 4; i++)
#pragma unroll
            for (int j = 0; j < 4; j++) s[i][j] = 0.f;
#pragma unroll 4
        for (int kk = 0; kk < 64; kk += 4) {
            float4 a[4], bq[4];
#pragma unroll
            for (int i = 0; i < 4; i++)
                a[i] = *(const float4*)&Qs[(ty * 4 + i) * LDP + kk];
#pragma unroll
            for (int j = 0; j < 4; j++)
                bq[j] = *(const float4*)&Ks[(j * 16 + tx) * LDP + kk];
#pragma unroll
            for (int i = 0; i < 4; i++)
#pragma unroll
                for (int j = 0; j < 4; j++)
                    s[i][j] += a[i].x * bq[j].x + a[i].y * bq[j].y
                             + a[i].z * bq[j].z + a[i].w * bq[j].w;
        }

        // local row max -> red
#pragma unroll
        for (int i = 0; i < 4; i++) {
            float lm = fmaxf(fmaxf(s[i][0], s[i][1]), fmaxf(s[i][2], s[i][3]));
            red[(ty * 4 + i) * 16 + tx] = lm;
        }
        __syncthreads();

        if (tid < 64) {
            float tm = red[tid * 16];
#pragma unroll
            for (int t = 1; t < 16; t++) tm = fmaxf(tm, red[tid * 16 + t]);
            float mo = mprev[tid];
            float mn = fmaxf(mo, tm);
            mnew[tid] = mn;
            fct[tid] = __expf(mo - mn);
            mprev[tid] = mn;
        }
        __syncthreads();

        // exponentiate + store P (cols j*16+tx) + local row sums
#pragma unroll
        for (int i = 0; i < 4; i++) {
            float mn = mnew[ty * 4 + i];
            float ls = 0.f;
#pragma unroll
            for (int j = 0; j < 4; j++) {
                float p = __expf(s[i][j] - mn);
                Ps[(ty * 4 + i) * LDP + j * 16 + tx] = p;
                ls += p;
            }
            red[(ty * 4 + i) * 16 + tx] = ls;
        }
        __syncthreads();

        if (tid < 64) {
            float ssum = 0.f;
#pragma unroll
            for (int t = 0; t < 16; t++) ssum += red[tid * 16 + t];
            lsum[tid] = lsum[tid] * fct[tid] + ssum;
        }

        // rescale O and accumulate O += P @ V (cols tx*4+j)
#pragma unroll
        for (int i = 0; i < 4; i++) {
            float f = fct[ty * 4 + i];
#pragma unroll
            for (int j = 0; j < 4; j++) o[i][j] *= f;
        }
#pragma unroll 4
        for (int key = 0; key < 64; key += 4) {
            float4 pa[4], vb[4];
#pragma unroll
            for (int i = 0; i < 4; i++)
                pa[i] = *(const float4*)&Ps[(ty * 4 + i) * LDP + key];
#pragma unroll
            for (int t = 0; t < 4; t++)
                vb[t] = *(const float4*)&Vs[(key + t) * LDP + tx * 4];
#pragma unroll
            for (int i = 0; i < 4; i++) {
                o[i][0] += pa[i].x * vb[0].x + pa[i].y * vb[1].x
                         + pa[i].z * vb[2].x + pa[i].w * vb[3].x;
                o[i][1] += pa[i].x * vb[0].y + pa[i].y * vb[1].y
                         + pa[i].z * vb[2].y + pa[i].w * vb[3].y;
                o[i][2] += pa[i].x * vb[0].z + pa[i].y * vb[1].z
                         + pa[i].z * vb[2].z + pa[i].w * vb[3].z;
                o[i][3] += pa[i].x * vb[0].w + pa[i].y * vb[1].w
                         + pa[i].z * vb[2].w + pa[i].w * vb[3].w;
            }
        }
        __syncthreads();       // all reads of Ks/Vs/Ps done

        if (more) {
#pragma unroll
            for (int p = 0; p < 4; p++) {
                int idx = tid + p * 256;
                int row = idx >> 4;
                int c4 = (idx & 15) << 2;
                *(float4*)&Ks[row * LDP + c4] = kreg[p];
                *(float4*)&Vs[row * LDP + c4] = vreg[p];
            }
            __syncthreads();
        }
    }

    // finalize: divide by l, write to [B,S,C]
#pragma unroll
    for (int i = 0; i < 4; i++) {
        float inv = 1.0f / lsum[ty * 4 + i];
        long off = baseoff + (long)(q0 + ty * 4 + i) * C_DIM + tx * 4;
        float4 v;
        v.x = o[i][0] * inv; v.y = o[i][1] * inv;
        v.z = o[i][2] * inv; v.w = o[i][3] * inv;
        *(float4*)(Ob + off) = v;
    }
}

// ------------------------- launch ------------------------------------------
extern "C" void kernel_launch(void* const* d_in, const int* in_sizes, int n_in,
                              void* d_out, int out_size)
{
    const float* x  = (const float*)d_in[0];
    const float* Wq = (const float*)d_in[1];
    const float* Wk = (const float*)d_in[2];
    const float* Wv = (const float*)d_in[3];
    const float* Wo = (const float*)d_in[4];
    const float* bo = (const float*)d_in[5];
    const float* Aq = (const float*)d_in[6];
    const float* Bq = (const float*)d_in[7];
    const float* Ak = (const float*)d_in[8];
    const float* Bk = (const float*)d_in[9];
    const float* Av = (const float*)d_in[10];
    const float* Bv = (const float*)d_in[11];
    const float* Ao = (const float*)d_in[12];
    const float* Bo = (const float*)d_in[13];

    float *weff, *qkv, *attno;
    cudaGetSymbolAddress((void**)&weff, g_weff);
    cudaGetSymbolAddress((void**)&qkv, g_qkv);
    cudaGetSymbolAddress((void**)&attno, g_attno);

    // 1) effective weights
    build_weff_kernel<<<dim3((C_DIM * C_DIM) / 256, 4), 256>>>(
        Wq, Wk, Wv, Wo, Aq, Bq, Ak, Bk, Av, Bv, Ao, Bo);

    // 2) fused Q/K/V projections: [4096,1280] = x @ weff[z]^T
    const long wStride = (long)C_DIM * C_DIM;
    const long oStride = (long)M_DIM * C_DIM;
    sgemm_bt_kernel<<<dim3(C_DIM / BN, M_DIM / BM, 3), 256>>>(
        x, weff, nullptr, qkv, M_DIM, C_DIM, C_DIM, wStride, oStride);

    // 3) attention
    size_t smem = (size_t)(4 * 64 * LDP + 64 * 16 + 4 * 64) * sizeof(float);
    cudaFuncSetAttribute(flash_kernel,
                         cudaFuncAttributeMaxDynamicSharedMemorySize, (int)smem);
    flash_kernel<<<dim3(S_DIM / 64, H_DIM, B_DIM), 256, smem>>>(
        qkv, qkv + oStride, qkv + 2 * oStride, attno);

    // 4) output projection (+bias) straight into d_out
    sgemm_bt_kernel<<<dim3(C_DIM / BN, M_DIM / BM, 1), 256>>>(
        attno, weff + 3 * wStride, bo, (float*)d_out,
        M_DIM, C_DIM, C_DIM, 0, 0);
}